// round 16
// baseline (speedup 1.0000x reference)
#include <cuda_runtime.h>
#include <cuda_bf16.h>
#include <stdint.h>

// Sbert idf-weighted masked mean pooling — split meta kernel + packed-metadata streamer.
// hidden [B, L, D] f32, ids [B, L] i32, mask [B, L] i32, idf [V] f32
// out[b,d] = sum_l hidden[b,l,d] * (mask[b,l] ? idf[ids[b,l]] : 0) / max(sum_l mask[b,l], 1e-9)
//
// ~50% of tokens have weight exactly 0 -> their hidden rows are never read
// (fmaf(h,0,acc)==acc bit-exactly). Kernel 1 compacts per-row metadata as a
// single float2 {weight, float4-offset as float bits} with the row offset
// PREMULTIPLIED by D4 — so the streamer's per-row address path is one LDS.64
// and one LEA (was: 2x LDS.32 + IMAD.WIDE), cutting the in-order-issue
// overhead in front of each LDG.128 group.

constexpr int L  = 100;
constexpr int D  = 768;
constexpr int D4 = D / 4;          // 192 float4 lanes per full row
constexpr int SPLIT = 3;           // column segments per row
constexpr int SEG4  = D4 / SPLIT;  // 64 float4 lanes per segment
constexpr int THREADS2 = SEG4;     // 64 threads per streamer CTA
constexpr int MAXB = 4096;
constexpr int MSTRIDE = 104;       // padded metadata row stride

// ── global scratch (static __device__ arrays: allowed) ──
__device__ float2 g_meta[MAXB * MSTRIDE];   // {weight, __int_as_float(row*D4)}
__device__ int    g_nnz [MAXB];
__device__ float  g_inv [MAXB];

// ── Kernel 1: one warp per batch row; ballot-based order-preserving compaction ──
constexpr int K1_WARPS = 8;
__global__ __launch_bounds__(K1_WARPS * 32) void sbert_meta_kernel(
    const int*   __restrict__ ids,
    const int*   __restrict__ mask,
    const float* __restrict__ idf,
    int B)
{
    const int lane = threadIdx.x & 31;
    const int b = blockIdx.x * K1_WARPS + (threadIdx.x >> 5);
    if (b >= B) return;

    int cnt = 0;     // mask count (denominator)
    int base = 0;    // compacted write cursor
    #pragma unroll
    for (int c = 0; c < 4; ++c) {
        const int tk = c * 32 + lane;
        const bool valid = (tk < L);
        int m = 0;
        float wv = 0.0f;
        if (valid) {
            const int g = b * L + tk;
            m = mask[g];
            if (m) wv = idf[ids[g]];
        }
        cnt += __popc(__ballot_sync(0xFFFFFFFFu, m != 0));
        const unsigned nzb = __ballot_sync(0xFFFFFFFFu, wv != 0.0f);
        if (wv != 0.0f) {
            const int pos = base + __popc(nzb & ((1u << lane) - 1u));
            g_meta[b * MSTRIDE + pos] =
                make_float2(wv, __int_as_float(tk * D4));   // premultiplied offset
        }
        base += __popc(nzb);
    }
    if (lane == 0) {
        g_nnz[b] = base;
        g_inv[b] = 1.0f / fmaxf((float)cnt, 1e-9f);
    }
}

// ── Kernel 2: fine-grained streamer. CTA (b, part) covers 256 columns. ──
__global__ __launch_bounds__(THREADS2) void sbert_pool_kernel(
    const float* __restrict__ hidden,
    float*       __restrict__ out)
{
    __shared__ __align__(16) float2 meta_s[MSTRIDE];

    const int b    = blockIdx.x / SPLIT;
    const int part = blockIdx.x % SPLIT;
    const int t    = threadIdx.x;

    // flat metadata burst: independent loads, one barrier
    const int   nnz = g_nnz[b];
    const float inv = g_inv[b];
    {
        meta_s[t] = g_meta[b * MSTRIDE + t];
        const int t2 = t + THREADS2;
        if (t2 < MSTRIDE) meta_s[t2] = g_meta[b * MSTRIDE + t2];
    }
    __syncthreads();

    const int lane4 = part * SEG4 + t;   // this thread's float4 column
    const float4* __restrict__ hp =
        reinterpret_cast<const float4*>(hidden + (size_t)b * L * D) + lane4;

    float4 acc = make_float4(0.f, 0.f, 0.f, 0.f);
    #pragma unroll 4
    for (int j = 0; j < nnz; ++j) {
        const float2 md = meta_s[j];               // one LDS.64
        const float4 h  = hp[__float_as_int(md.y)]; // LEA + LDG.128
        const float  wj = md.x;
        acc.x = fmaf(h.x, wj, acc.x);
        acc.y = fmaf(h.y, wj, acc.y);
        acc.z = fmaf(h.z, wj, acc.z);
        acc.w = fmaf(h.w, wj, acc.w);
    }

    acc.x *= inv; acc.y *= inv; acc.z *= inv; acc.w *= inv;
    reinterpret_cast<float4*>(out + (size_t)b * D)[lane4] = acc;
}

extern "C" void kernel_launch(void* const* d_in, const int* in_sizes, int n_in,
                              void* d_out, int out_size) {
    const float* hidden = (const float*)d_in[0];
    const int*   ids    = (const int*)  d_in[1];
    const int*   mask   = (const int*)  d_in[2];
    const float* idf    = (const float*)d_in[3];
    float*       out    = (float*)d_out;

    const int B = out_size / D;   // 4096
    const int g1 = (B + K1_WARPS - 1) / K1_WARPS;
    sbert_meta_kernel<<<g1, K1_WARPS * 32>>>(ids, mask, idf, B);
    sbert_pool_kernel<<<B * SPLIT, THREADS2>>>(hidden, out);
}